// round 1
// baseline (speedup 1.0000x reference)
#include <cuda_runtime.h>

// Problem constants
#define Bb  16
#define FIN 3
#define Nn  170
#define Tt  288
#define Hh  64
#define Oo  64
#define Kk  3
#define KSS 3

// Scratch: [B,T,N,O] intermediate (coalesced along O), transposed to [B,O,N,T] by kernel 2.
__device__ float g_tmp[(size_t)Bb * Tt * Nn * Oo];   // ~200 MB, static device array (allowed)

// ---------------- shared memory layout (in floats) ----------------
// u    : [510][64]      u_k rows stacked over k (32640)
// tmT  : [64][172]      conv output transposed, m-contiguous (11008)
// thk  : [64][64]       theta_k staged per k (4096)
// csm  : [176][33]      cheb chunk, natural [n][m-chunk] (5808)
// sxs  : [9][170]       x slice (f,s,n) (1530)
// cw/cb/rw/rb           conv + residual params
constexpr int TMT_STRIDE = 172;
constexpr int CSM_STRIDE = 33;
constexpr int U_OFF   = 0;
constexpr int U_SZ    = (Kk * Nn) * 64;             // 32640
constexpr int TMT_OFF = U_OFF + U_SZ;               // 32640
constexpr int TMT_SZ  = 64 * TMT_STRIDE;            // 11008
constexpr int THK_OFF = TMT_OFF + TMT_SZ;           // 43648
constexpr int THK_SZ  = 64 * 64;                    // 4096
constexpr int CSM_OFF = THK_OFF + THK_SZ;           // 47744
constexpr int CSM_SZ  = 176 * CSM_STRIDE;           // 5808
constexpr int SXS_OFF = CSM_OFF + CSM_SZ;           // 53552
constexpr int SXS_SZ  = 9 * Nn;                     // 1530
constexpr int CW_OFF  = SXS_OFF + SXS_SZ;           // 55082
constexpr int CB_OFF  = CW_OFF + 576;
constexpr int RW_OFF  = CB_OFF + 64;
constexpr int RB_OFF  = RW_OFF + 192;
constexpr int SMEM_FLOATS = RB_OFF + 64 + 16;       // +slack for benign OOB tile reads
constexpr int SMEM_BYTES  = SMEM_FLOATS * 4;        // ~224 KB

#define FMA4(a, s, v) { (a).x = fmaf((s),(v).x,(a).x); (a).y = fmaf((s),(v).y,(a).y); \
                        (a).z = fmaf((s),(v).z,(a).z); (a).w = fmaf((s),(v).w,(a).w); }

__global__ __launch_bounds__(384, 1)
void stgcn_main(const float* __restrict__ x,     const float* __restrict__ cheb,
                const float* __restrict__ convw, const float* __restrict__ convb,
                const float* __restrict__ theta, const float* __restrict__ resw,
                const float* __restrict__ resb)
{
    extern __shared__ float sm[];
    float* su  = sm + U_OFF;
    float* tmT = sm + TMT_OFF;
    float* thk = sm + THK_OFF;
    float* csm = sm + CSM_OFF;
    float* sxs = sm + SXS_OFF;
    float* scw = sm + CW_OFF;
    float* scb = sm + CB_OFF;
    float* srw = sm + RW_OFF;
    float* srb = sm + RB_OFF;

    const int t   = blockIdx.x;    // 0..287
    const int b   = blockIdx.y;    // 0..15
    const int tid = threadIdx.x;   // 0..383

    // ---- stage small params + x time-slice (with temporal zero-pad) ----
    for (int i = tid; i < 576; i += 384) scw[i] = convw[i];
    for (int i = tid; i < 64;  i += 384) { scb[i] = convb[i]; srb[i] = resb[i]; }
    for (int i = tid; i < 192; i += 384) srw[i] = resw[i];
    for (int i = tid; i < 9 * Nn; i += 384) {
        int seg = i / Nn, n = i - seg * Nn;
        int f = seg / 3, s = seg - f * 3;
        int ts = t - 1 + s;
        float v = 0.f;
        if (ts >= 0 && ts < Tt) v = x[((b * FIN + f) * Nn + n) * Tt + ts];
        sxs[seg * Nn + n] = v;
    }
    __syncthreads();

    // ---- phase A: temporal conv + ReLU -> tmT[h][m] (m-contiguous) ----
    for (int i = tid; i < 64 * TMT_STRIDE; i += 384) {
        int h = i / TMT_STRIDE, m = i - h * TMT_STRIDE;
        float v = 0.f;
        if (m < Nn) {
            v = scb[h];
            #pragma unroll
            for (int f = 0; f < 3; f++)
                #pragma unroll
                for (int s = 0; s < 3; s++)
                    v = fmaf(scw[h * 9 + f * 3 + s], sxs[(f * 3 + s) * Nn + m], v);
            v = fmaxf(v, 0.f);
        }
        tmT[i] = v;
    }

    // thread roles
    const int o_grpB = tid & 15, m_grp = tid >> 4;   // phase B grid: 22(m) x 16(o), 8m x 4o per thread
    const int o_grpC = tid & 7,  n_grp = tid >> 3;   // phase C grid: 44(n) x 8(o), 4n x 8o per thread
    const bool actB = (m_grp < 22);
    const bool actC = (n_grp < 44);

    float4 acc0[4], acc1[4];   // persistent gcn accumulators: 4 n-rows x 8 o (2 float4)
    #pragma unroll
    for (int i = 0; i < 4; i++) {
        acc0[i] = make_float4(0.f, 0.f, 0.f, 0.f);
        acc1[i] = make_float4(0.f, 0.f, 0.f, 0.f);
    }

    for (int k = 0; k < Kk; k++) {
        __syncthreads();                                   // u & thk free
        for (int i = tid; i < 4096; i += 384) thk[i] = theta[k * 4096 + i];
        __syncthreads();                                   // thk + tmT ready

        // ---- phase B: u_k[m][o] = sum_c tmT[c][m] * thk[c][o] ----
        if (actB) {
            float4 bacc[8];
            #pragma unroll
            for (int i = 0; i < 8; i++) bacc[i] = make_float4(0.f, 0.f, 0.f, 0.f);
            const float* tr = tmT + m_grp * 8;
            const float* th = thk + o_grpB * 4;
            #pragma unroll 4
            for (int c = 0; c < 64; c++) {
                float4 tv0 = *(const float4*)(tr + c * TMT_STRIDE);
                float4 tv1 = *(const float4*)(tr + c * TMT_STRIDE + 4);
                float4 th4 = *(const float4*)(th + c * 64);
                FMA4(bacc[0], tv0.x, th4); FMA4(bacc[1], tv0.y, th4);
                FMA4(bacc[2], tv0.z, th4); FMA4(bacc[3], tv0.w, th4);
                FMA4(bacc[4], tv1.x, th4); FMA4(bacc[5], tv1.y, th4);
                FMA4(bacc[6], tv1.z, th4); FMA4(bacc[7], tv1.w, th4);
            }
            #pragma unroll
            for (int i = 0; i < 8; i++) {
                int m = m_grp * 8 + i;
                if (m < Nn) *(float4*)(su + (k * Nn + m) * 64 + o_grpB * 4) = bacc[i];
            }
        }
        __syncthreads();                                   // u_k ready

        // ---- phase C: acc[n][o] += cheb_k[n][m] * u_k[m][o], m in 6 chunks ----
        for (int mc = 0; mc < 6; mc++) {
            const int m0 = mc * 32;
            const int mw = (Nn - m0 < 32) ? (Nn - m0) : 32;
            for (int i = tid; i < Nn * 32; i += 384) {
                int n = i >> 5, j = i & 31;
                if (j < mw) csm[n * CSM_STRIDE + j] = cheb[(k * Nn + n) * Nn + m0 + j];
            }
            __syncthreads();
            if (actC) {
                const float* crow = csm + (n_grp * 4) * CSM_STRIDE;
                const float* ur   = su + (k * Nn + m0) * 64 + o_grpC * 8;
                auto body = [&](int mm) {
                    float4 u0 = *(const float4*)(ur + mm * 64);
                    float4 u1 = *(const float4*)(ur + mm * 64 + 4);
                    float c0 = crow[mm];
                    float c1 = crow[CSM_STRIDE + mm];
                    float c2 = crow[2 * CSM_STRIDE + mm];
                    float c3 = crow[3 * CSM_STRIDE + mm];
                    FMA4(acc0[0], c0, u0); FMA4(acc1[0], c0, u1);
                    FMA4(acc0[1], c1, u0); FMA4(acc1[1], c1, u1);
                    FMA4(acc0[2], c2, u0); FMA4(acc1[2], c2, u1);
                    FMA4(acc0[3], c3, u0); FMA4(acc1[3], c3, u1);
                };
                if (mw == 32) {
                    #pragma unroll 8
                    for (int mm = 0; mm < 32; mm++) body(mm);
                } else {
                    for (int mm = 0; mm < mw; mm++) body(mm);
                }
            }
            __syncthreads();
        }
    }

    // ---- epilogue: ReLU + residual, write to g_tmp[b][t][n][o] ----
    if (actC) {
        const int ob = o_grpC * 8;
        #pragma unroll
        for (int i = 0; i < 4; i++) {
            const int n = n_grp * 4 + i;
            if (n >= Nn) continue;
            const float xv0 = sxs[(0 * 3 + 1) * Nn + n];
            const float xv1 = sxs[(1 * 3 + 1) * Nn + n];
            const float xv2 = sxs[(2 * 3 + 1) * Nn + n];
            float vals[8] = { acc0[i].x, acc0[i].y, acc0[i].z, acc0[i].w,
                              acc1[i].x, acc1[i].y, acc1[i].z, acc1[i].w };
            #pragma unroll
            for (int j = 0; j < 8; j++) {
                int o = ob + j;
                float g = fmaxf(vals[j], 0.f);
                g += srb[o];
                g = fmaf(srw[o * 3 + 0], xv0, g);
                g = fmaf(srw[o * 3 + 1], xv1, g);
                g = fmaf(srw[o * 3 + 2], xv2, g);
                vals[j] = g;
            }
            float* dst = g_tmp + (((size_t)(b * Tt + t) * Nn + n) * 64) + ob;
            *(float4*)dst       = make_float4(vals[0], vals[1], vals[2], vals[3]);
            *(float4*)(dst + 4) = make_float4(vals[4], vals[5], vals[6], vals[7]);
        }
    }
}

// ---- kernel 2: [B,T,N,O] -> [B,O,N,T], coalesced both sides via smem tile ----
__global__ __launch_bounds__(256)
void stgcn_transpose(float* __restrict__ out)
{
    extern __shared__ float smt[];                // [288][65]
    const int n = blockIdx.x;
    const int b = blockIdx.y;
    const float* src = g_tmp + ((size_t)(b * Tt) * Nn + n) * 64;
    for (int i = threadIdx.x; i < Tt * 64; i += 256) {
        int tt = i >> 6, o = i & 63;
        smt[tt * 65 + o] = src[(size_t)tt * (Nn * 64) + o];
    }
    __syncthreads();
    for (int i = threadIdx.x; i < 64 * Tt; i += 256) {
        int o = i / Tt, tt = i - o * Tt;
        out[((b * 64 + o) * Nn + n) * Tt + tt] = smt[tt * 65 + o];
    }
}

extern "C" void kernel_launch(void* const* d_in, const int* in_sizes, int n_in,
                              void* d_out, int out_size)
{
    (void)in_sizes; (void)n_in; (void)out_size;
    const float* x     = (const float*)d_in[0];
    // d_in[1] = adj (unused by forward)
    const float* cheb  = (const float*)d_in[2];
    const float* convw = (const float*)d_in[3];
    const float* convb = (const float*)d_in[4];
    const float* theta = (const float*)d_in[5];
    const float* resw  = (const float*)d_in[6];
    const float* resb  = (const float*)d_in[7];
    float* out = (float*)d_out;

    cudaFuncSetAttribute(stgcn_main, cudaFuncAttributeMaxDynamicSharedMemorySize, SMEM_BYTES);
    cudaFuncSetAttribute(stgcn_transpose, cudaFuncAttributeMaxDynamicSharedMemorySize, Tt * 65 * 4);

    dim3 g1(Tt, Bb);
    stgcn_main<<<g1, 384, SMEM_BYTES>>>(x, cheb, convw, convb, theta, resw, resb);

    dim3 g2(Nn, Bb);
    stgcn_transpose<<<g2, 256, Tt * 65 * 4>>>(out);
}

// round 3
// speedup vs baseline: 1.0012x; 1.0012x over previous
#include <cuda_runtime.h>

// Problem constants
#define Bb  16
#define FIN 3
#define Nn  170
#define Tt  288
#define Hh  64
#define Oo  64
#define Kk  3
#define KSS 3

// Scratch: [B,T,N,O] intermediate (coalesced along O), transposed to [B,O,N,T] by kernel 2.
__device__ float g_tmp[(size_t)Bb * Tt * Nn * Oo];   // ~200 MB, static device array (allowed)

// ---------------- shared memory layout (in floats) ----------------
// u    : [510][64]      u_k rows stacked over k (32640)
// tmT  : [64][172]      conv output transposed, m-contiguous (11008)
// thk  : [64][64]       theta_k staged per k (4096)
// csm  : [176][33]      cheb chunk, natural [n][m-chunk] (5808)
// sxs  : [9][170]       x slice (f,s,n) (1530)
// cw/cb/rw/rb           conv + residual params
constexpr int TMT_STRIDE = 172;
constexpr int CSM_STRIDE = 33;
constexpr int U_OFF   = 0;
constexpr int U_SZ    = (Kk * Nn) * 64;             // 32640
constexpr int TMT_OFF = U_OFF + U_SZ;               // 32640
constexpr int TMT_SZ  = 64 * TMT_STRIDE;            // 11008
constexpr int THK_OFF = TMT_OFF + TMT_SZ;           // 43648
constexpr int THK_SZ  = 64 * 64;                    // 4096
constexpr int CSM_OFF = THK_OFF + THK_SZ;           // 47744
constexpr int CSM_SZ  = 176 * CSM_STRIDE;           // 5808
constexpr int SXS_OFF = CSM_OFF + CSM_SZ;           // 53552
constexpr int SXS_SZ  = 9 * Nn;                     // 1530
constexpr int CW_OFF  = SXS_OFF + SXS_SZ;           // 55082
constexpr int CB_OFF  = CW_OFF + 576;
constexpr int RW_OFF  = CB_OFF + 64;
constexpr int RB_OFF  = RW_OFF + 192;
constexpr int SMEM_FLOATS = RB_OFF + 64 + 16;       // +slack for benign OOB tile reads
constexpr int SMEM_BYTES  = SMEM_FLOATS * 4;        // ~224 KB

#define FMA4(a, s, v) { (a).x = fmaf((s),(v).x,(a).x); (a).y = fmaf((s),(v).y,(a).y); \
                        (a).z = fmaf((s),(v).z,(a).z); (a).w = fmaf((s),(v).w,(a).w); }

__global__ __launch_bounds__(384, 1)
void stgcn_main(const float* __restrict__ x,     const float* __restrict__ cheb,
                const float* __restrict__ convw, const float* __restrict__ convb,
                const float* __restrict__ theta, const float* __restrict__ resw,
                const float* __restrict__ resb)
{
    extern __shared__ float sm[];
    float* su  = sm + U_OFF;
    float* tmT = sm + TMT_OFF;
    float* thk = sm + THK_OFF;
    float* csm = sm + CSM_OFF;
    float* sxs = sm + SXS_OFF;
    float* scw = sm + CW_OFF;
    float* scb = sm + CB_OFF;
    float* srw = sm + RW_OFF;
    float* srb = sm + RB_OFF;

    const int t   = blockIdx.x;    // 0..287
    const int b   = blockIdx.y;    // 0..15
    const int tid = threadIdx.x;   // 0..383

    // ---- stage small params + x time-slice (with temporal zero-pad) ----
    for (int i = tid; i < 576; i += 384) scw[i] = convw[i];
    for (int i = tid; i < 64;  i += 384) { scb[i] = convb[i]; srb[i] = resb[i]; }
    for (int i = tid; i < 192; i += 384) srw[i] = resw[i];
    for (int i = tid; i < 9 * Nn; i += 384) {
        int seg = i / Nn, n = i - seg * Nn;
        int f = seg / 3, s = seg - f * 3;
        int ts = t - 1 + s;
        float v = 0.f;
        if (ts >= 0 && ts < Tt) v = x[((b * FIN + f) * Nn + n) * Tt + ts];
        sxs[seg * Nn + n] = v;
    }
    __syncthreads();

    // ---- phase A: temporal conv + ReLU -> tmT[h][m] (m-contiguous) ----
    for (int i = tid; i < 64 * TMT_STRIDE; i += 384) {
        int h = i / TMT_STRIDE, m = i - h * TMT_STRIDE;
        float v = 0.f;
        if (m < Nn) {
            v = scb[h];
            #pragma unroll
            for (int f = 0; f < 3; f++)
                #pragma unroll
                for (int s = 0; s < 3; s++)
                    v = fmaf(scw[h * 9 + f * 3 + s], sxs[(f * 3 + s) * Nn + m], v);
            v = fmaxf(v, 0.f);
        }
        tmT[i] = v;
    }

    // thread roles
    const int o_grpB = tid & 15, m_grp = tid >> 4;   // phase B grid: 22(m) x 16(o), 8m x 4o per thread
    const int o_grpC = tid & 7,  n_grp = tid >> 3;   // phase C grid: 44(n) x 8(o), 4n x 8o per thread
    const bool actB = (m_grp < 22);
    const bool actC = (n_grp < 44);

    float4 acc0[4], acc1[4];   // persistent gcn accumulators: 4 n-rows x 8 o (2 float4)
    #pragma unroll
    for (int i = 0; i < 4; i++) {
        acc0[i] = make_float4(0.f, 0.f, 0.f, 0.f);
        acc1[i] = make_float4(0.f, 0.f, 0.f, 0.f);
    }

    for (int k = 0; k < Kk; k++) {
        __syncthreads();                                   // u & thk free
        for (int i = tid; i < 4096; i += 384) thk[i] = theta[k * 4096 + i];
        __syncthreads();                                   // thk + tmT ready

        // ---- phase B: u_k[m][o] = sum_c tmT[c][m] * thk[c][o] ----
        if (actB) {
            float4 bacc[8];
            #pragma unroll
            for (int i = 0; i < 8; i++) bacc[i] = make_float4(0.f, 0.f, 0.f, 0.f);
            const float* tr = tmT + m_grp * 8;
            const float* th = thk + o_grpB * 4;
            #pragma unroll 4
            for (int c = 0; c < 64; c++) {
                float4 tv0 = *(const float4*)(tr + c * TMT_STRIDE);
                float4 tv1 = *(const float4*)(tr + c * TMT_STRIDE + 4);
                float4 th4 = *(const float4*)(th + c * 64);
                FMA4(bacc[0], tv0.x, th4); FMA4(bacc[1], tv0.y, th4);
                FMA4(bacc[2], tv0.z, th4); FMA4(bacc[3], tv0.w, th4);
                FMA4(bacc[4], tv1.x, th4); FMA4(bacc[5], tv1.y, th4);
                FMA4(bacc[6], tv1.z, th4); FMA4(bacc[7], tv1.w, th4);
            }
            #pragma unroll
            for (int i = 0; i < 8; i++) {
                int m = m_grp * 8 + i;
                if (m < Nn) *(float4*)(su + (k * Nn + m) * 64 + o_grpB * 4) = bacc[i];
            }
        }
        __syncthreads();                                   // u_k ready

        // ---- phase C: acc[n][o] += cheb_k[n][m] * u_k[m][o], m in 6 chunks ----
        for (int mc = 0; mc < 6; mc++) {
            const int m0 = mc * 32;
            const int mw = (Nn - m0 < 32) ? (Nn - m0) : 32;
            for (int i = tid; i < Nn * 32; i += 384) {
                int n = i >> 5, j = i & 31;
                if (j < mw) csm[n * CSM_STRIDE + j] = cheb[(k * Nn + n) * Nn + m0 + j];
            }
            __syncthreads();
            if (actC) {
                const float* crow = csm + (n_grp * 4) * CSM_STRIDE;
                const float* ur   = su + (k * Nn + m0) * 64 + o_grpC * 8;
                auto body = [&](int mm) {
                    float4 u0 = *(const float4*)(ur + mm * 64);
                    float4 u1 = *(const float4*)(ur + mm * 64 + 4);
                    float c0 = crow[mm];
                    float c1 = crow[CSM_STRIDE + mm];
                    float c2 = crow[2 * CSM_STRIDE + mm];
                    float c3 = crow[3 * CSM_STRIDE + mm];
                    FMA4(acc0[0], c0, u0); FMA4(acc1[0], c0, u1);
                    FMA4(acc0[1], c1, u0); FMA4(acc1[1], c1, u1);
                    FMA4(acc0[2], c2, u0); FMA4(acc1[2], c2, u1);
                    FMA4(acc0[3], c3, u0); FMA4(acc1[3], c3, u1);
                };
                if (mw == 32) {
                    #pragma unroll 8
                    for (int mm = 0; mm < 32; mm++) body(mm);
                } else {
                    for (int mm = 0; mm < mw; mm++) body(mm);
                }
            }
            __syncthreads();
        }
    }

    // ---- epilogue: ReLU + residual, write to g_tmp[b][t][n][o] ----
    if (actC) {
        const int ob = o_grpC * 8;
        #pragma unroll
        for (int i = 0; i < 4; i++) {
            const int n = n_grp * 4 + i;
            if (n >= Nn) continue;
            const float xv0 = sxs[(0 * 3 + 1) * Nn + n];
            const float xv1 = sxs[(1 * 3 + 1) * Nn + n];
            const float xv2 = sxs[(2 * 3 + 1) * Nn + n];
            float vals[8] = { acc0[i].x, acc0[i].y, acc0[i].z, acc0[i].w,
                              acc1[i].x, acc1[i].y, acc1[i].z, acc1[i].w };
            #pragma unroll
            for (int j = 0; j < 8; j++) {
                int o = ob + j;
                float g = fmaxf(vals[j], 0.f);
                g += srb[o];
                g = fmaf(srw[o * 3 + 0], xv0, g);
                g = fmaf(srw[o * 3 + 1], xv1, g);
                g = fmaf(srw[o * 3 + 2], xv2, g);
                vals[j] = g;
            }
            float* dst = g_tmp + (((size_t)(b * Tt + t) * Nn + n) * 64) + ob;
            *(float4*)dst       = make_float4(vals[0], vals[1], vals[2], vals[3]);
            *(float4*)(dst + 4) = make_float4(vals[4], vals[5], vals[6], vals[7]);
        }
    }
}

// ---- kernel 2: [B,T,N,O] -> [B,O,N,T], coalesced both sides via smem tile ----
__global__ __launch_bounds__(256)
void stgcn_transpose(float* __restrict__ out)
{
    extern __shared__ float smt[];                // [288][65]
    const int n = blockIdx.x;
    const int b = blockIdx.y;
    const float* src = g_tmp + ((size_t)(b * Tt) * Nn + n) * 64;
    for (int i = threadIdx.x; i < Tt * 64; i += 256) {
        int tt = i >> 6, o = i & 63;
        smt[tt * 65 + o] = src[(size_t)tt * (Nn * 64) + o];
    }
    __syncthreads();
    for (int i = threadIdx.x; i < 64 * Tt; i += 256) {
        int o = i / Tt, tt = i - o * Tt;
        out[((b * 64 + o) * Nn + n) * Tt + tt] = smt[tt * 65 + o];
    }
}

extern "C" void kernel_launch(void* const* d_in, const int* in_sizes, int n_in,
                              void* d_out, int out_size)
{
    (void)in_sizes; (void)n_in; (void)out_size;
    const float* x     = (const float*)d_in[0];
    // d_in[1] = adj (unused by forward)
    const float* cheb  = (const float*)d_in[2];
    const float* convw = (const float*)d_in[3];
    const float* convb = (const float*)d_in[4];
    const float* theta = (const float*)d_in[5];
    const float* resw  = (const float*)d_in[6];
    const float* resb  = (const float*)d_in[7];
    float* out = (float*)d_out;

    cudaFuncSetAttribute(stgcn_main, cudaFuncAttributeMaxDynamicSharedMemorySize, SMEM_BYTES);
    cudaFuncSetAttribute(stgcn_transpose, cudaFuncAttributeMaxDynamicSharedMemorySize, Tt * 65 * 4);

    dim3 g1(Tt, Bb);
    stgcn_main<<<g1, 384, SMEM_BYTES>>>(x, cheb, convw, convb, theta, resw, resb);

    dim3 g2(Nn, Bb);
    stgcn_transpose<<<g2, 256, Tt * 65 * 4>>>(out);
}